// round 15
// baseline (speedup 1.0000x reference)
#include <cuda_runtime.h>

// Problem sizes (fixed by the dataset)
#define BB 8
#define LL 2048
#define DD 128
#define CC 64              // chunks per batch
#define LC 32              // events per chunk (LL / CC)
#define EPSC 1e-6f

// Chunk z-sums T'[b,c,:] = sum_{j in c} m_j e_j exp(beta*(t_j - t_mid_b)),
// anchored at the batch midpoint time (exponents bounded by ~±12.5).
__device__ float g_T[BB * CC * DD];        // 256 KB
// Pre-staged per-event factors (computed in K1, read sequentially in K2):
// layout [g][0..31]=w, [g][32..63]=v, [g][64..95]=beta*u.
__device__ float g_aux[BB * CC * 96];      // 192 KB

// ---------------------------------------------------------------------------
// K1: one block (256 thr) per chunk. Gather E rows into REGISTERS only
// (thread tid holds f4-slice tid&31 of rows 8*it+(tid>>5)), weight by w_j,
// warp-partial z-sums -> combine -> g_T. Also stages w/v/bu to g_aux and
// zeroes out[b]. No smem E pass, two __syncthreads total.
// ---------------------------------------------------------------------------
__global__ void __launch_bounds__(256) k1_zsum(
    const int*   __restrict__ ids,
    const float* __restrict__ times,
    const float* __restrict__ mask,
    const float* __restrict__ emb,
    const float* __restrict__ u_table,
    const float* __restrict__ beta_p,
    float*       __restrict__ out)
{
    __shared__ float4 s_zsum[8 * 32];
    __shared__ float  s_w[LC];

    const int tid  = threadIdx.x;
    const int w    = tid >> 5;
    const int lane = tid & 31;
    const int g    = blockIdx.x;           // b*CC + c
    const int b    = g >> 6;
    const int c    = g & (CC - 1);
    const int base = b * LL + c * LC;

    // Gather: 4 rows per thread, all LDGs front-batched.
    const float4* embv = (const float4*)emb;
    float4 ebuf[4];
#pragma unroll
    for (int it = 0; it < 4; ++it) {
        int row = it * 8 + w;              // (it*256+tid)>>5
        int id  = __ldg(&ids[base + row]);
        ebuf[it] = embv[(size_t)id * 32 + lane];
    }

    const float beta = beta_p[0];
    const float ta   = times[b * LL + LL / 2];

    if (c == 0 && tid == 0) out[b] = 0.f;  // visible to K2 via kernel boundary

    if (tid < LC) {
        float t  = times[base + tid];
        float m  = mask[base + tid];
        int   id = ids[base + tid];
        float wv = m * __expf(beta * (t - ta));
        s_w[tid] = wv;
        g_aux[g * 96 + tid]      = wv;                    // w
        g_aux[g * 96 + 32 + tid] = __expf(-beta * (t - ta)); // v
        g_aux[g * 96 + 64 + tid] = beta * u_table[id];    // beta*u
    }
    __syncthreads();

    // Per-thread weighted sum over its 4 rows (pure register FMA).
    float4 zz = {0.f, 0.f, 0.f, 0.f};
#pragma unroll
    for (int it = 0; it < 4; ++it) {
        float wz = s_w[it * 8 + w];
        zz.x += wz * ebuf[it].x; zz.y += wz * ebuf[it].y;
        zz.z += wz * ebuf[it].z; zz.w += wz * ebuf[it].w;
    }
    s_zsum[w * 32 + lane] = zz;
    __syncthreads();

    if (tid < 32) {
        float4 T = {0.f, 0.f, 0.f, 0.f};
#pragma unroll
        for (int p = 0; p < 8; ++p) {
            float4 a = s_zsum[p * 32 + tid];
            T.x += a.x; T.y += a.y; T.z += a.z; T.w += a.w;
        }
        ((float4*)g_T)[g * 32 + tid] = T;
    }
}

// ---------------------------------------------------------------------------
// K2: one block (256 thr, 8 warps) per chunk. g_T is valid at launch (graph
// edge). At instruction 0: issue carry loads (L2) AND the E re-gather (L2-hot
// from K1) AND the aux loads. Then one combined scan+dot pass, reduce, log,
// one atomicAdd per chunk. No inter-block synchronization anywhere.
// ---------------------------------------------------------------------------
__global__ void __launch_bounds__(256) k2_scan(
    const int*   __restrict__ ids,
    const float* __restrict__ emb,
    float*       __restrict__ out)
{
    __shared__ float4 s_E4[LC * 32];       // 16 KB
    __shared__ float4 s_zsum[8 * 32];      // 4 KB
    __shared__ float4 s_carry[8 * 32];     // 4 KB
    __shared__ float  s_pp[LC][33];        // 4.2 KB
    __shared__ float  s_aux[96];           // w | v | bu
    __shared__ float  s_r[LC];

    const int tid  = threadIdx.x;
    const int w    = tid >> 5;
    const int lane = tid & 31;
    const int g    = blockIdx.x;           // b*CC + c
    const int b    = g >> 6;
    const int c    = g & (CC - 1);
    const int base = b * LL + c * LC;

    // ---- Instruction 0: carry loads (warp w covers chunks w*8..w*8+7) ----
    const float4* Tb = (const float4*)g_T + (b * CC) * 32;
    float4 A0 = {0,0,0,0}, A1 = {0,0,0,0};
    const int c2b = w * 8;
#pragma unroll
    for (int k = 0; k < 8; k += 2) {
        if (c2b + k     < c) { float4 T = Tb[(c2b + k    ) * 32 + lane];
            A0.x += T.x; A0.y += T.y; A0.z += T.z; A0.w += T.w; }
        if (c2b + k + 1 < c) { float4 T = Tb[(c2b + k + 1) * 32 + lane];
            A1.x += T.x; A1.y += T.y; A1.z += T.z; A1.w += T.w; }
    }

    // ---- E re-gather (ids and rows are L2-hot from K1) ----
    const float4* embv = (const float4*)emb;
    float4 ebuf[4];
#pragma unroll
    for (int it = 0; it < 4; ++it) {
        int idx = it * 256 + tid;
        int row = idx >> 5, f4 = idx & 31;
        int id  = __ldg(&ids[base + row]);
        ebuf[it] = embv[(size_t)id * 32 + f4];
    }

    // ---- Aux (sequential, L2) ----
    if (tid < 96) s_aux[tid] = g_aux[g * 96 + tid];

    {
        float4 P;
        P.x = A0.x + A1.x; P.y = A0.y + A1.y;
        P.z = A0.z + A1.z; P.w = A0.w + A1.w;
        s_carry[w * 32 + lane] = P;
    }
#pragma unroll
    for (int it = 0; it < 4; ++it) s_E4[it * 256 + tid] = ebuf[it];
    __syncthreads();

    // ---- Per-warp z partials over the warp's own 4 events ----
    {
        float4 zz = {0.f, 0.f, 0.f, 0.f};
#pragma unroll
        for (int k = 0; k < 4; ++k) {
            int j = w * 4 + k;
            float wz = s_aux[j];
            float4 e = s_E4[j * 32 + lane];
            zz.x += wz * e.x; zz.y += wz * e.y; zz.z += wz * e.z; zz.w += wz * e.w;
        }
        s_zsum[w * 32 + lane] = zz;
    }
    __syncthreads();

    // ---- Combined: Acc = carry-A + z-prefix(<w), then scan+dot in one pass
    {
        float4 Acc = {0.f, 0.f, 0.f, 0.f};
#pragma unroll
        for (int p = 0; p < 8; ++p) {
            float4 a = s_carry[p * 32 + lane];
            Acc.x += a.x; Acc.y += a.y; Acc.z += a.z; Acc.w += a.w;
            if (p < w) {
                float4 z = s_zsum[p * 32 + lane];
                Acc.x += z.x; Acc.y += z.y; Acc.z += z.z; Acc.w += z.w;
            }
        }
#pragma unroll
        for (int k = 0; k < 4; ++k) {
            int i = w * 4 + k;
            float4 e = s_E4[i * 32 + lane];
            s_pp[i][lane] = e.x * Acc.x + e.y * Acc.y + e.z * Acc.z + e.w * Acc.w;
            float wz = s_aux[i];
            Acc.x += wz * e.x; Acc.y += wz * e.y;
            Acc.z += wz * e.z; Acc.w += wz * e.w;
        }
    }
    __syncthreads();

    // ---- 8 threads per event reduce its 32 lane-partials; parallel logs ----
    {
        int e = tid >> 3, q = tid & 7;
        float s = 0.f;
#pragma unroll
        for (int k = 0; k < 4; ++k) s += s_pp[e][q * 4 + k];
        s += __shfl_xor_sync(0xffffffffu, s, 1);
        s += __shfl_xor_sync(0xffffffffu, s, 2);
        s += __shfl_xor_sync(0xffffffffu, s, 4);
        if (q == 0) {
            float lam = s_aux[64 + e] * s_aux[32 + e] * s;   // bu * v * dot
            s_r[e] = __logf(lam + EPSC);
        }
    }
    __syncthreads();

    if (tid < 32) {
        float lg = s_r[tid];
        lg += __shfl_xor_sync(0xffffffffu, lg, 16);
        lg += __shfl_xor_sync(0xffffffffu, lg, 8);
        lg += __shfl_xor_sync(0xffffffffu, lg, 4);
        lg += __shfl_xor_sync(0xffffffffu, lg, 2);
        lg += __shfl_xor_sync(0xffffffffu, lg, 1);
        if (tid == 0) atomicAdd(&out[b], lg);
    }
}

// ---------------------------------------------------------------------------
extern "C" void kernel_launch(void* const* d_in, const int* in_sizes, int n_in,
                              void* d_out, int out_size)
{
    const int*   ids   = (const int*)d_in[0];
    const float* times = (const float*)d_in[1];
    const float* mask  = (const float*)d_in[2];
    const float* emb   = (const float*)d_in[3];
    const float* u_tab = (const float*)d_in[4];
    const float* beta  = (const float*)d_in[5];
    float* out = (float*)d_out;

    k1_zsum<<<BB * CC, 256>>>(ids, times, mask, emb, u_tab, beta, out);
    k2_scan<<<BB * CC, 256>>>(ids, emb, out);
}

// round 16
// speedup vs baseline: 1.1682x; 1.1682x over previous
#include <cuda_runtime.h>

// Problem sizes (fixed by the dataset)
#define BB 8
#define LL 2048
#define DD 128
#define CC 64              // chunks per batch (legacy granularity)
#define EV 128             // events per block
#define QQ 16              // blocks (super-chunks) per batch
#define EPSC 1e-6f

// Super-chunk z-sums U[b,q,:] = sum_{j in q} m_j e_j exp(beta*(t_j - ta_b)),
// anchored at the batch midpoint time (exponents bounded by ~±12.5).
__device__ float    g_U[BB * QQ * DD];     // 64 KB
// Per-batch monotone barrier tickets, padded to one 128B line each.
// Never reset: each launch adds QQ per batch; target = next multiple of QQ.
__device__ unsigned g_cnt[BB * 32];

// ---------------------------------------------------------------------------
// ONE fused kernel: 128 blocks (one per SM), 512 threads / 16 warps.
// Block (b,q) owns events [q*128, q*128+128) of batch b.
// Warp w owns events w*8..w*8+7 AND holds their embedding rows in REGISTERS
// (lane = float4 slice): E never touches shared memory.
//
// Global-anchor factorization: exp(-beta(t_i-t_j)) = v_i * w_j,
//   w_j = m_j exp(beta(t_j-ta)), v_i = exp(-beta(t_i-ta)), ta = batch mid.
// lam_i = bu_i v_i * e_i . (A_q + H_i),
//   A_q = sum_{q2<q} U[b,q2]          (unweighted cross-block carry)
//   H_i = in-block prefix of w_j e_j  (16-warp z-prefix + in-warp scan)
// ---------------------------------------------------------------------------
__global__ void __launch_bounds__(512) hawkes_fused(
    const int*   __restrict__ ids,
    const float* __restrict__ times,
    const float* __restrict__ mask,
    const float* __restrict__ emb,
    const float* __restrict__ u_table,
    const float* __restrict__ beta_p,
    float*       __restrict__ out)
{
    __shared__ float4 s_zsum[16 * 32];     // per-warp z partials (8 KB)
    __shared__ float4 s_carry[16 * 32];    // per-warp carry rows   (8 KB)
    __shared__ float  s_pp[EV][33];        // per-lane dot partials (16.9 KB)
    __shared__ float  s_w[EV], s_v[EV], s_bu[EV];
    __shared__ float  s_r[EV];
    __shared__ float  s_red[4];

    const int tid  = threadIdx.x;
    const int w    = tid >> 5;             // warp 0..15
    const int lane = tid & 31;
    const int g    = blockIdx.x;           // b*QQ + q
    const int b    = g >> 4;
    const int q    = g & (QQ - 1);
    const int base = b * LL + q * EV;

    // ---- Gather: warp w loads ITS 8 events' rows into registers.
    //      Each iteration: one 512B row, 32 lanes x LDG.128, fully coalesced.
    const float4* embv = (const float4*)emb;
    float4 ebuf[8];
#pragma unroll
    for (int it = 0; it < 8; ++it) {
        int row = w * 8 + it;              // this warp's event
        int id  = __ldg(&ids[base + row]); // warp-broadcast load
        ebuf[it] = embv[(size_t)id * 32 + lane];
    }

    // ---- Overlapped precompute (batch-anchored factors) ----
    const float beta = beta_p[0];
    const float ta   = times[b * LL + LL / 2];

    if (q == 0 && tid == 0) out[b] = 0.f;  // released by the fence below

    if (tid < EV) {
        float t  = times[base + tid];
        float m  = mask[base + tid];
        int   id = ids[base + tid];
        s_w [tid] = m * __expf(beta * (t - ta));   // |exponent| <= ~12.5
        s_v [tid] = __expf(-beta * (t - ta));
        s_bu[tid] = beta * u_table[id];
    }
    __syncthreads();

    // ---- Per-warp z-sums (register FMAs against own rows) ----
    {
        float4 zz = {0.f, 0.f, 0.f, 0.f};
#pragma unroll
        for (int it = 0; it < 8; ++it) {
            float wz = s_w[w * 8 + it];
            zz.x += wz * ebuf[it].x; zz.y += wz * ebuf[it].y;
            zz.z += wz * ebuf[it].z; zz.w += wz * ebuf[it].w;
        }
        s_zsum[w * 32 + lane] = zz;
    }
    __syncthreads();

    // ---- Super-chunk sum U -> gmem; fence; ARRIVE (non-blocking) ----
    if (tid < 32) {
        float4 U = {0.f, 0.f, 0.f, 0.f};
#pragma unroll
        for (int p = 0; p < 16; ++p) {
            float4 a = s_zsum[p * 32 + tid];
            U.x += a.x; U.y += a.y; U.z += a.z; U.w += a.w;
        }
        ((float4*)g_U)[g * 32 + tid] = U;
    }
    __syncthreads();
    __threadfence();                        // release g_U (and out[b]=0)
    unsigned target = 0;
    if (tid == 0) {
        unsigned t = atomicAdd(&g_cnt[b * 32], 1u);
        target = ((t >> 4) + 1u) << 4;      // next multiple of QQ=16
    }

    // ---- Pre-barrier: in-block scan (carry A folded in later) ----
    {
        float4 H = {0.f, 0.f, 0.f, 0.f};
#pragma unroll
        for (int p = 0; p < 15; ++p) {
            if (p < w) {                    // warp-uniform predicate
                float4 z = s_zsum[p * 32 + lane];
                H.x += z.x; H.y += z.y; H.z += z.z; H.w += z.w;
            }
        }
#pragma unroll
        for (int it = 0; it < 8; ++it) {
            int i = w * 8 + it;
            float4 e = ebuf[it];
            s_pp[i][lane] = e.x * H.x + e.y * H.y + e.z * H.z + e.w * H.w;
            float wz = s_w[i];
            H.x += wz * e.x; H.y += wz * e.y; H.z += wz * e.z; H.w += wz * e.w;
        }
    }

    // ---- WAIT ----
    if (tid == 0) {
        unsigned cur;
        for (;;) {
            asm volatile("ld.global.acquire.gpu.u32 %0, [%1];"
                         : "=r"(cur) : "l"(&g_cnt[b * 32]));
            if (cur >= target) break;
            __nanosleep(64);
        }
    }
    __syncthreads();

    // ---- Carry: warp w fetches U[b,w] iff w < q (one 512B row each) ----
    {
        float4 P = {0.f, 0.f, 0.f, 0.f};
        if (w < q) P = ((const float4*)g_U)[(b * QQ + w) * 32 + lane];
        s_carry[w * 32 + lane] = P;
    }
    __syncthreads();

    // ---- Fold e_i . A into pp (A block-constant) ----
    {
        float4 A = {0.f, 0.f, 0.f, 0.f};
#pragma unroll
        for (int p = 0; p < 16; ++p) {
            float4 a = s_carry[p * 32 + lane];
            A.x += a.x; A.y += a.y; A.z += a.z; A.w += a.w;
        }
#pragma unroll
        for (int it = 0; it < 8; ++it) {
            int i = w * 8 + it;
            float4 e = ebuf[it];
            s_pp[i][lane] += e.x * A.x + e.y * A.y + e.z * A.z + e.w * A.w;
        }
    }
    __syncthreads();

    // ---- 4 threads per event reduce its 32 lane-partials; parallel logs ----
    {
        int e = tid >> 2, q4 = tid & 3;
        float s = 0.f;
#pragma unroll
        for (int k = 0; k < 8; ++k) s += s_pp[e][q4 * 8 + k];  // conflict-free
        s += __shfl_xor_sync(0xffffffffu, s, 1);
        s += __shfl_xor_sync(0xffffffffu, s, 2);
        if (q4 == 0) {
            float lam = s_bu[e] * s_v[e] * s;
            s_r[e] = __logf(lam + EPSC);
        }
    }
    __syncthreads();

    // ---- Block log-sum: 4 warps reduce 32 each -> single atomicAdd ----
    if (tid < EV) {
        float lg = s_r[tid];
        lg += __shfl_xor_sync(0xffffffffu, lg, 16);
        lg += __shfl_xor_sync(0xffffffffu, lg, 8);
        lg += __shfl_xor_sync(0xffffffffu, lg, 4);
        lg += __shfl_xor_sync(0xffffffffu, lg, 2);
        lg += __shfl_xor_sync(0xffffffffu, lg, 1);
        if (lane == 0) s_red[tid >> 5] = lg;
    }
    __syncthreads();
    if (tid == 0)
        atomicAdd(&out[b], (s_red[0] + s_red[1]) + (s_red[2] + s_red[3]));
}

// ---------------------------------------------------------------------------
extern "C" void kernel_launch(void* const* d_in, const int* in_sizes, int n_in,
                              void* d_out, int out_size)
{
    const int*   ids   = (const int*)d_in[0];
    const float* times = (const float*)d_in[1];
    const float* mask  = (const float*)d_in[2];
    const float* emb   = (const float*)d_in[3];
    const float* u_tab = (const float*)d_in[4];
    const float* beta  = (const float*)d_in[5];
    float* out = (float*)d_out;

    hawkes_fused<<<BB * QQ, 512>>>(ids, times, mask, emb, u_tab, beta, out);
}

// round 17
// speedup vs baseline: 1.1719x; 1.0031x over previous
#include <cuda_runtime.h>

// Problem sizes (fixed by the dataset)
#define BB 8
#define LL 2048
#define DD 128
#define EV 128             // events per block
#define QQ 16              // blocks (super-chunks) per batch
#define EPSC 1e-6f

// Super-chunk z-sums U[b,q,:] = sum_{j in q} m_j e_j exp(beta*(t_j - ta_b)),
// anchored at the batch midpoint time (exponents bounded by ~±12.5).
__device__ float    g_U[BB * QQ * DD];     // 64 KB
// Per-batch monotone barrier tickets, padded to one 128B line each.
// Never reset: each launch adds QQ per batch; target = next multiple of QQ.
__device__ unsigned g_cnt[BB * 32];

// ---------------------------------------------------------------------------
// ONE fused kernel: 128 blocks (one per SM), 512 threads / 16 warps.
// Block (b,q) owns events [q*128, q*128+128). Warp w owns events w*8..w*8+7
// and holds their embedding rows in REGISTERS (lane = float4 slice).
//
// Critical-path layout:
//   gather -> zsum -> sync -> { warp0: U-store -> syncwarp -> lane0
//   fence+ARRIVE | all warps: in-block scan } -> sync -> tid0 WAIT -> sync
//   -> per-warp direct carry loads + fold -> sync -> reduce/log -> sync ->
//   one atomicAdd.
// ---------------------------------------------------------------------------
__global__ void __launch_bounds__(512) hawkes_fused(
    const int*   __restrict__ ids,
    const float* __restrict__ times,
    const float* __restrict__ mask,
    const float* __restrict__ emb,
    const float* __restrict__ u_table,
    const float* __restrict__ beta_p,
    float*       __restrict__ out)
{
    __shared__ float4 s_zsum[16 * 32];     // per-warp z partials (8 KB)
    __shared__ float  s_pp[EV][33];        // per-lane dot partials (16.9 KB)
    __shared__ float  s_w[EV], s_v[EV], s_bu[EV];
    __shared__ float  s_r[EV];
    __shared__ float  s_red[4];
    __shared__ unsigned s_target;

    const int tid  = threadIdx.x;
    const int w    = tid >> 5;             // warp 0..15
    const int lane = tid & 31;
    const int g    = blockIdx.x;           // b*QQ + q
    const int b    = g >> 4;
    const int q    = g & (QQ - 1);
    const int base = b * LL + q * EV;

    // ---- Gather: warp w loads ITS 8 events' rows into registers ----
    const float4* embv = (const float4*)emb;
    float4 ebuf[8];
#pragma unroll
    for (int it = 0; it < 8; ++it) {
        int row = w * 8 + it;
        int id  = __ldg(&ids[base + row]); // warp-broadcast load
        ebuf[it] = embv[(size_t)id * 32 + lane];
    }

    // ---- Overlapped precompute (batch-anchored factors) ----
    const float beta = beta_p[0];
    const float ta   = times[b * LL + LL / 2];

    if (q == 0 && tid == 0) out[b] = 0.f;  // ordered by warp0's fence below

    if (tid < EV) {
        float t  = times[base + tid];
        float m  = mask[base + tid];
        int   id = ids[base + tid];
        s_w [tid] = m * __expf(beta * (t - ta));   // |exponent| <= ~12.5
        s_v [tid] = __expf(-beta * (t - ta));
        s_bu[tid] = beta * u_table[id];
    }
    __syncthreads();

    // ---- Per-warp z-sums (register FMAs against own rows) ----
    float wreg[8];
#pragma unroll
    for (int it = 0; it < 8; ++it) wreg[it] = s_w[w * 8 + it];
    {
        float4 zz = {0.f, 0.f, 0.f, 0.f};
#pragma unroll
        for (int it = 0; it < 8; ++it) {
            float wz = wreg[it];
            zz.x += wz * ebuf[it].x; zz.y += wz * ebuf[it].y;
            zz.z += wz * ebuf[it].z; zz.w += wz * ebuf[it].w;
        }
        s_zsum[w * 32 + lane] = zz;
    }
    __syncthreads();

    // ---- Warp 0: U-sum + store + fence + ARRIVE (concurrent with scans) ----
    if (w == 0) {
        float4 U = {0.f, 0.f, 0.f, 0.f};
#pragma unroll
        for (int p = 0; p < 16; ++p) {
            float4 a = s_zsum[p * 32 + lane];
            U.x += a.x; U.y += a.y; U.z += a.z; U.w += a.w;
        }
        ((float4*)g_U)[g * 32 + lane] = U;
        __syncwarp();
        if (lane == 0) {
            __threadfence();               // release g_U (and out[b]=0)
            unsigned t = atomicAdd(&g_cnt[b * 32], 1u);
            s_target = ((t >> 4) + 1u) << 4;   // next multiple of QQ=16
        }
    }

    // ---- All warps: in-block scan (carry A folded in later) ----
    {
        float4 H = {0.f, 0.f, 0.f, 0.f};
#pragma unroll
        for (int p = 0; p < 15; ++p) {
            if (p < w) {                    // warp-uniform predicate
                float4 z = s_zsum[p * 32 + lane];
                H.x += z.x; H.y += z.y; H.z += z.z; H.w += z.w;
            }
        }
#pragma unroll
        for (int it = 0; it < 8; ++it) {
            int i = w * 8 + it;
            float4 e = ebuf[it];
            s_pp[i][lane] = e.x * H.x + e.y * H.y + e.z * H.z + e.w * H.w;
            float wz = wreg[it];
            H.x += wz * e.x; H.y += wz * e.y; H.z += wz * e.z; H.w += wz * e.w;
        }
    }
    __syncthreads();

    // ---- WAIT ----
    if (tid == 0) {
        unsigned target = s_target, cur;
        for (;;) {
            asm volatile("ld.global.acquire.gpu.u32 %0, [%1];"
                         : "=r"(cur) : "l"(&g_cnt[b * 32]));
            if (cur >= target) break;
            __nanosleep(64);
        }
    }
    __syncthreads();

    // ---- Carry: each warp sums U[b,p] for p<q directly (L1/L2-hot) ----
    {
        const float4* U4 = (const float4*)g_U + (b * QQ) * 32;
        float4 A0 = {0,0,0,0}, A1 = {0,0,0,0}, A2 = {0,0,0,0}, A3 = {0,0,0,0};
#pragma unroll
        for (int p = 0; p < 15; p += 4) {
            if (p     < q) { float4 a = U4[(p    ) * 32 + lane];
                A0.x += a.x; A0.y += a.y; A0.z += a.z; A0.w += a.w; }
            if (p + 1 < q) { float4 a = U4[(p + 1) * 32 + lane];
                A1.x += a.x; A1.y += a.y; A1.z += a.z; A1.w += a.w; }
            if (p + 2 < q) { float4 a = U4[(p + 2) * 32 + lane];
                A2.x += a.x; A2.y += a.y; A2.z += a.z; A2.w += a.w; }
            if (p + 3 < q && p + 3 < 15) { float4 a = U4[(p + 3) * 32 + lane];
                A3.x += a.x; A3.y += a.y; A3.z += a.z; A3.w += a.w; }
        }
        float4 A;
        A.x = (A0.x + A1.x) + (A2.x + A3.x);
        A.y = (A0.y + A1.y) + (A2.y + A3.y);
        A.z = (A0.z + A1.z) + (A2.z + A3.z);
        A.w = (A0.w + A1.w) + (A2.w + A3.w);
#pragma unroll
        for (int it = 0; it < 8; ++it) {
            int i = w * 8 + it;
            float4 e = ebuf[it];
            s_pp[i][lane] += e.x * A.x + e.y * A.y + e.z * A.z + e.w * A.w;
        }
    }
    __syncthreads();

    // ---- 4 threads per event reduce its 32 lane-partials; parallel logs ----
    {
        int e = tid >> 2, q4 = tid & 3;
        float s = 0.f;
#pragma unroll
        for (int k = 0; k < 8; ++k) s += s_pp[e][q4 * 8 + k];  // conflict-free
        s += __shfl_xor_sync(0xffffffffu, s, 1);
        s += __shfl_xor_sync(0xffffffffu, s, 2);
        if (q4 == 0) {
            float lam = s_bu[e] * s_v[e] * s;
            s_r[e] = __logf(lam + EPSC);
        }
    }
    __syncthreads();

    // ---- Block log-sum: 4 warps reduce 32 each -> single atomicAdd ----
    if (tid < EV) {
        float lg = s_r[tid];
        lg += __shfl_xor_sync(0xffffffffu, lg, 16);
        lg += __shfl_xor_sync(0xffffffffu, lg, 8);
        lg += __shfl_xor_sync(0xffffffffu, lg, 4);
        lg += __shfl_xor_sync(0xffffffffu, lg, 2);
        lg += __shfl_xor_sync(0xffffffffu, lg, 1);
        if (lane == 0) s_red[tid >> 5] = lg;
    }
    __syncthreads();
    if (tid == 0)
        atomicAdd(&out[b], (s_red[0] + s_red[1]) + (s_red[2] + s_red[3]));
}

// ---------------------------------------------------------------------------
extern "C" void kernel_launch(void* const* d_in, const int* in_sizes, int n_in,
                              void* d_out, int out_size)
{
    const int*   ids   = (const int*)d_in[0];
    const float* times = (const float*)d_in[1];
    const float* mask  = (const float*)d_in[2];
    const float* emb   = (const float*)d_in[3];
    const float* u_tab = (const float*)d_in[4];
    const float* beta  = (const float*)d_in[5];
    float* out = (float*)d_out;

    hawkes_fused<<<BB * QQ, 512>>>(ids, times, mask, emb, u_tab, beta, out);
}